// round 17
// baseline (speedup 1.0000x reference)
#include <cuda_runtime.h>
#include <cuda_bf16.h>
#include <cstdint>

#define BB   4
#define NQ   16384
#define MM   4096
#define CC   256
#define BN   (BB*NQ)
#define GC   4096            // 16^3 cells per batch

typedef unsigned long long u64;
typedef unsigned int       u32;

// ---------------- scratch (static device memory; no allocations) ----------------
__device__ float4 g_w[BN];            // per-query 3 weights
__device__ int4   g_i[BN];            // per-query 3 neighbor indices
__device__ float  g_ft[BB*MM*CC];     // transposed features (B, M, C), 16.8 MB
__device__ int    g_cnt[BB*GC];       // cell counts
__device__ int    g_start[BB*(GC+1)]; // exclusive starts
__device__ int    g_cur[BB*GC];       // scatter cursors
__device__ float4 g_ord[BB*MM];       // grid-ordered points (x,y,z,|k|^2)
__device__ int    g_oidx[BB*MM];      // original indices of ordered points

static __device__ __forceinline__ float f_inf() { return __int_as_float(0x7f800000); }

// Squared norm with LLVM DAGCombiner contraction order (bit-matches reference):
static __device__ __forceinline__ float norm2_llvm(float x, float y, float z) {
    return fmaf(z, z, fmaf(x, x, __fmul_rn(y, y)));
}

// monotone float <-> ordered-u32
static __device__ __forceinline__ u32 ordf(float f) {
    u32 u = __float_as_uint(f);
    u32 m = (u32)((int)u >> 31) | 0x80000000u;
    return u ^ m;
}
static __device__ __forceinline__ float deord(u32 e) {
    return __uint_as_float((e & 0x80000000u) ? (e ^ 0x80000000u) : ~e);
}

static __device__ __forceinline__ int cell_of(float x, float y, float z) {
    int cx = min((int)(x * 16.0f), 15); cx = max(cx, 0);
    int cy = min((int)(y * 16.0f), 15); cy = max(cy, 0);
    int cz = min((int)(z * 16.0f), 15); cz = max(cz, 0);
    return (cz * 16 + cy) * 16 + cx;
}

// packed f32x2 fma (sm_103a): d = a*b + c per 32-bit lane, rn each lane
union f2u { unsigned long long u; float2 f; };
#define FMA2(d, a, b, c) \
    asm("fma.rn.f32x2 %0, %1, %2, %3;" : "=l"(d) : "l"(a), "l"(b), "l"(c))

// ---------------- grid build kernels ----------------
__global__ void __launch_bounds__(256) zero_kernel() {
    int i = blockIdx.x * 256 + threadIdx.x;
    if (i < BB * GC) g_cnt[i] = 0;
}

__global__ void __launch_bounds__(256) count_kernel(const float* __restrict__ known) {
    int p = blockIdx.x * 256 + threadIdx.x;     // 0..BB*MM-1
    int b = p >> 12;
    float x = known[(size_t)p * 3 + 0];
    float y = known[(size_t)p * 3 + 1];
    float z = known[(size_t)p * 3 + 2];
    atomicAdd(&g_cnt[b * GC + cell_of(x, y, z)], 1);
}

__global__ void __launch_bounds__(1024) scan_kernel() {
    __shared__ int part[1024];
    int b   = blockIdx.x;
    int tid = threadIdx.x;
    int v0 = g_cnt[b * GC + 4 * tid + 0];
    int v1 = g_cnt[b * GC + 4 * tid + 1];
    int v2 = g_cnt[b * GC + 4 * tid + 2];
    int v3 = g_cnt[b * GC + 4 * tid + 3];
    part[tid] = v0 + v1 + v2 + v3;
    __syncthreads();
    for (int off = 1; off < 1024; off <<= 1) {
        int x = (tid >= off) ? part[tid - off] : 0;
        __syncthreads();
        part[tid] += x;
        __syncthreads();
    }
    int base = (tid > 0) ? part[tid - 1] : 0;
    int s0 = base, s1 = s0 + v0, s2 = s1 + v1, s3 = s2 + v2;
    g_start[b * (GC + 1) + 4 * tid + 0] = s0;
    g_start[b * (GC + 1) + 4 * tid + 1] = s1;
    g_start[b * (GC + 1) + 4 * tid + 2] = s2;
    g_start[b * (GC + 1) + 4 * tid + 3] = s3;
    g_cur[b * GC + 4 * tid + 0] = s0;
    g_cur[b * GC + 4 * tid + 1] = s1;
    g_cur[b * GC + 4 * tid + 2] = s2;
    g_cur[b * GC + 4 * tid + 3] = s3;
    if (tid == 1023) g_start[b * (GC + 1) + GC] = MM;
}

__global__ void __launch_bounds__(256) scatter_kernel(const float* __restrict__ known) {
    int p = blockIdx.x * 256 + threadIdx.x;
    int b = p >> 12;
    int i = p & (MM - 1);
    float x = known[(size_t)p * 3 + 0];
    float y = known[(size_t)p * 3 + 1];
    float z = known[(size_t)p * 3 + 2];
    int slot = atomicAdd(&g_cur[b * GC + cell_of(x, y, z)], 1);
    g_ord[b * MM + slot]  = make_float4(x, y, z, norm2_llvm(x, y, z));
    g_oidx[b * MM + slot] = i;
}

// ---------------- kernel 1: transpose feats (B,C,M) -> (B,M,C) ----------------
__global__ void __launch_bounds__(256) tr_kernel(const float* __restrict__ f) {
    __shared__ float t[32][33];
    int b  = blockIdx.z;
    int m0 = blockIdx.x * 32;
    int c0 = blockIdx.y * 32;
    const float* fb = f + (size_t)b * CC * MM;
#pragma unroll
    for (int i = threadIdx.y; i < 32; i += 8)
        t[i][threadIdx.x] = fb[(size_t)(c0 + i) * MM + m0 + threadIdx.x];
    __syncthreads();
    float* fo = g_ft + (size_t)b * MM * CC;
#pragma unroll
    for (int i = threadIdx.y; i < 32; i += 8)
        fo[(size_t)(m0 + i) * CC + c0 + threadIdx.x] = t[threadIdx.x][i];
}

// ---------------- kernel 2: 3-NN + inverse-distance weights ----------------
// Top-3 kept as u64 keys (ord(d2)<<12 | idx): exact lexicographic (d2, idx)
// selection = top_k value-then-lowest-index tie-break, order-independent.
// Phase A: exact scan of the query's 27-cell grid neighborhood -> tight thr.
// Phase B: FFMA2 packed screen over all 4096; exact path dedupes re-encounters
// by key equality. Exact d2 rounding (bit-matches reference):
//   su,kk = fma(z,z, fma(x,x, y*y));  dot = fma(z,uz, fma(y,uy, x*ux));
//   d2    = (su + kk) - 2*dot
__device__ __forceinline__ void ins_key(u64 k, u64& b0, u64& b1, u64& b2) {
    if (k == b0 || k == b1 || k == b2) return;   // dedupe re-encounters
    if (k < b2) {
        if (k < b1) {
            b2 = b1;
            if (k < b0) { b1 = b0; b0 = k; } else b1 = k;
        } else b2 = k;
    }
}

#define KNN_PROCK(kx, ky, kz, kw, gj) do {                                     \
    float _dt = fmaf((kz), uz, fmaf((ky), uy, __fmul_rn((kx), ux)));           \
    float _d2 = __fadd_rn(__fadd_rn(su, (kw)), -__fmul_rn(2.0f, _dt));         \
    u64 _k = ((u64)ordf(_d2) << 12) | (u32)(gj);                               \
    ins_key(_k, b0, b1, b2);                                                   \
} while (0)

__global__ void __launch_bounds__(256) knn_kernel(const float* __restrict__ unknown,
                                                  const float* __restrict__ known) {
    __shared__ __align__(16) float skx[2048];
    __shared__ __align__(16) float sky[2048];
    __shared__ __align__(16) float skz[2048];
    __shared__ __align__(16) float skk[2048];

    int qid = blockIdx.x * 256 + threadIdx.x;   // all threads of a block share batch b
    int b   = qid >> 14;
    const float* kb = known + (size_t)b * MM * 3;

    float ux = unknown[(size_t)qid * 3 + 0];
    float uy = unknown[(size_t)qid * 3 + 1];
    float uz = unknown[(size_t)qid * 3 + 2];
    float su = norm2_llvm(ux, uy, uz);
    float nux = __fmul_rn(-2.0f, ux);
    float nuy = __fmul_rn(-2.0f, uy);
    float nuz = __fmul_rn(-2.0f, uz);
    f2u nux2, nuy2, nuz2;
    nux2.f = make_float2(nux, nux);
    nuy2.f = make_float2(nuy, nuy);
    nuz2.f = make_float2(nuz, nuz);

    // keys init to encode(+inf) | 0xFFF  -> deord gives +inf, never equal to real keys
    u64 kinit = ((u64)0xFF800000u << 12) | 0xFFFu;
    u64 b0 = kinit, b1 = kinit, b2 = kinit;

    // ---- Phase A: 27-cell neighborhood warm-start (exact inserts) ----
    {
        int cx = max(0, min((int)(ux * 16.0f), 15));
        int cy = max(0, min((int)(uy * 16.0f), 15));
        int cz = max(0, min((int)(uz * 16.0f), 15));
        int x0 = max(cx - 1, 0), x1 = min(cx + 1, 15);
        int y0 = max(cy - 1, 0), y1 = min(cy + 1, 15);
        int z0 = max(cz - 1, 0), z1 = min(cz + 1, 15);
        const int*    st = g_start + b * (GC + 1);
        const float4* od = g_ord   + b * MM;
        const int*    oi = g_oidx  + b * MM;
        for (int zz = z0; zz <= z1; zz++)
            for (int yy = y0; yy <= y1; yy++) {
                int rowc = (zz * 16 + yy) * 16;
                int s = st[rowc + x0];
                int e = st[rowc + x1 + 1];
                for (int i = s; i < e; i++) {
                    float4 p = od[i];
                    int    gi = oi[i];
                    KNN_PROCK(p.x, p.y, p.z, p.w, gi);
                }
            }
    }
    float thr = __fadd_rn(__fadd_rn(deord((u32)(b2 >> 12)), -su), 6e-6f);

    // ---- Phase B: screened full scan ----
    for (int ch = 0; ch < 2; ch++) {
        int base = ch * 2048;
        __syncthreads();
        for (int p = threadIdx.x; p < 2048; p += 256) {
            float kx = kb[(size_t)(base + p) * 3 + 0];
            float ky = kb[(size_t)(base + p) * 3 + 1];
            float kz = kb[(size_t)(base + p) * 3 + 2];
            skx[p] = kx; sky[p] = ky; skz[p] = kz;
            skk[p] = norm2_llvm(kx, ky, kz);
        }
        __syncthreads();

        for (int j = 0; j < 2048; j += 8) {
            f2u x0, x1, x2, x3, y0, y1, y2, y3, z0, z1, z2, z3, w0, w1, w2, w3;
            ulonglong2 t;
            t = *(const ulonglong2*)(skx + j);     x0.u = t.x; x1.u = t.y;
            t = *(const ulonglong2*)(skx + j + 4); x2.u = t.x; x3.u = t.y;
            t = *(const ulonglong2*)(sky + j);     y0.u = t.x; y1.u = t.y;
            t = *(const ulonglong2*)(sky + j + 4); y2.u = t.x; y3.u = t.y;
            t = *(const ulonglong2*)(skz + j);     z0.u = t.x; z1.u = t.y;
            t = *(const ulonglong2*)(skz + j + 4); z2.u = t.x; z3.u = t.y;
            t = *(const ulonglong2*)(skk + j);     w0.u = t.x; w1.u = t.y;
            t = *(const ulonglong2*)(skk + j + 4); w2.u = t.x; w3.u = t.y;

            f2u v0, v1, v2, v3;
            FMA2(v0.u, z0.u, nuz2.u, w0.u);
            FMA2(v1.u, z1.u, nuz2.u, w1.u);
            FMA2(v2.u, z2.u, nuz2.u, w2.u);
            FMA2(v3.u, z3.u, nuz2.u, w3.u);
            FMA2(v0.u, y0.u, nuy2.u, v0.u);
            FMA2(v1.u, y1.u, nuy2.u, v1.u);
            FMA2(v2.u, y2.u, nuy2.u, v2.u);
            FMA2(v3.u, y3.u, nuy2.u, v3.u);
            FMA2(v0.u, x0.u, nux2.u, v0.u);
            FMA2(v1.u, x1.u, nux2.u, v1.u);
            FMA2(v2.u, x2.u, nux2.u, v2.u);
            FMA2(v3.u, x3.u, nux2.u, v3.u);

            float m0 = fminf(fminf(v0.f.x, v0.f.y), fminf(v1.f.x, v1.f.y));
            float m1 = fminf(fminf(v2.f.x, v2.f.y), fminf(v3.f.x, v3.f.y));
            if (fminf(m0, m1) < thr) {   // rare: exact reference-rounded inserts
                KNN_PROCK(x0.f.x, y0.f.x, z0.f.x, w0.f.x, base + j + 0);
                KNN_PROCK(x0.f.y, y0.f.y, z0.f.y, w0.f.y, base + j + 1);
                KNN_PROCK(x1.f.x, y1.f.x, z1.f.x, w1.f.x, base + j + 2);
                KNN_PROCK(x1.f.y, y1.f.y, z1.f.y, w1.f.y, base + j + 3);
                KNN_PROCK(x2.f.x, y2.f.x, z2.f.x, w2.f.x, base + j + 4);
                KNN_PROCK(x2.f.y, y2.f.y, z2.f.y, w2.f.y, base + j + 5);
                KNN_PROCK(x3.f.x, y3.f.x, z3.f.x, w3.f.x, base + j + 6);
                KNN_PROCK(x3.f.y, y3.f.y, z3.f.y, w3.f.y, base + j + 7);
                thr = __fadd_rn(__fadd_rn(deord((u32)(b2 >> 12)), -su), 6e-6f);
            }
        }
    }

    // unpack keys -> (d2, idx) in top_k order
    float d0 = deord((u32)(b0 >> 12));
    float d1 = deord((u32)(b1 >> 12));
    float d2v = deord((u32)(b2 >> 12));
    int   i0 = (int)(b0 & 0xFFFu);
    int   i1 = (int)(b1 & 0xFFFu);
    int   i2 = (int)(b2 & 0xFFFu);

    // weights: dist = sqrt(max(d2,0)); r = 1/(dist+eps); w = r / sum(r)
    float dd0 = sqrtf(fmaxf(d0, 0.0f));
    float dd1 = sqrtf(fmaxf(d1, 0.0f));
    float dd2 = sqrtf(fmaxf(d2v, 0.0f));
    float r0 = __fdiv_rn(1.0f, __fadd_rn(dd0, 1e-8f));
    float r1 = __fdiv_rn(1.0f, __fadd_rn(dd1, 1e-8f));
    float r2 = __fdiv_rn(1.0f, __fadd_rn(dd2, 1e-8f));
    float ws = __fadd_rn(__fadd_rn(r0, r1), r2);
    g_w[qid] = make_float4(__fdiv_rn(r0, ws), __fdiv_rn(r1, ws),
                           __fdiv_rn(r2, ws), 0.0f);
    g_i[qid] = make_int4(i0, i1, i2, 0);
}

// ---------------- kernel 3: coalesced gather + blend, transposed write ----------------
__global__ void __launch_bounds__(256) gather_kernel(float* __restrict__ out) {
    __shared__ float  tile[CC][33];
    __shared__ float4 sw[32];
    __shared__ int4   si[32];

    int blk = blockIdx.x;
    int b   = blk >> 9;
    int n0  = (blk & 511) << 5;
    int tid = threadIdx.x;

    if (tid < 32) {
        sw[tid] = g_w[b * NQ + n0 + tid];
        si[tid] = g_i[b * NQ + n0 + tid];
    }
    __syncthreads();

    const float* ftb = g_ft + (size_t)b * MM * CC;
    int c = tid;
#pragma unroll 4
    for (int q = 0; q < 32; q++) {
        int4   jj = si[q];
        float4 ww = sw[q];
        float f0 = __ldg(&ftb[(size_t)jj.x * CC + c]);
        float f1 = __ldg(&ftb[(size_t)jj.y * CC + c]);
        float f2 = __ldg(&ftb[(size_t)jj.z * CC + c]);
        tile[c][q] = fmaf(f2, ww.z, fmaf(f1, ww.y, __fmul_rn(f0, ww.x)));
    }
    __syncthreads();

    float* ob = out + (size_t)b * CC * NQ;
    int wrp = tid >> 5, lane = tid & 31;
#pragma unroll
    for (int r = wrp; r < CC; r += 8)
        ob[(size_t)r * NQ + n0 + lane] = tile[r][lane];
}

// ---------------- launch ----------------
extern "C" void kernel_launch(void* const* d_in, const int* in_sizes, int n_in,
                              void* d_out, int out_size) {
    const float* unknown = (const float*)d_in[0];   // (B, n, 3)
    const float* known   = (const float*)d_in[1];   // (B, m, 3)
    const float* feats   = (const float*)d_in[2];   // (B, C, m)
    float* out = (float*)d_out;                     // (B, C, n)

    // grid build (tiny)
    zero_kernel<<<(BB * GC + 255) / 256, 256>>>();
    count_kernel<<<(BB * MM + 255) / 256, 256>>>(known);
    scan_kernel<<<BB, 1024>>>();
    scatter_kernel<<<(BB * MM + 255) / 256, 256>>>(known);

    dim3 tb(32, 8);
    dim3 tg(MM / 32, CC / 32, BB);
    tr_kernel<<<tg, tb>>>(feats);

    knn_kernel<<<BN / 256, 256>>>(unknown, known);

    gather_kernel<<<BN / 32, 256>>>(out);
}